// round 13
// baseline (speedup 1.0000x reference)
#include <cuda_runtime.h>

// 2D Haar DWT, (16,64,256,256) fp32 -> 4 x (16,64,128,128).
// Butterfly form of the reference's dense DWT matrices:
//   LL=0.5(a+b+c+d) LH=0.5(a-b+c-d) HL=0.5(a+b-c-d) HH=0.5(a-b-c+d)
// HBM-bound streaming kernel: 256 MB read + 256 MB write (irreducible).
// Config notes (measured):
//   R11: 2-rows/thread (MLP=8, 40 regs) REGRESSED (occ 59%, DRAM 79.3%).
//   R12: 1-row/thread, 512-thr blocks, 32 regs, occ 72%, DRAM 81.8%, 74.66us.
//   R13: keep R12 mapping; stores use DEFAULT cache policy (drop .cs) so L2
//        can buffer dirty lines and batch DRAM write-backs into longer bursts
//        (less read/write turnaround). Loads stay .cs (never re-read).

static constexpr int NIMG = 16 * 64;        // 1024 images
static constexpr int H    = 256;
static constexpr int W    = 256;
static constexpr int LH_  = H / 2;          // 128
static constexpr int LW_  = W / 2;          // 128
static constexpr long long BAND = (long long)NIMG * LH_ * LW_;  // 16,777,216 per band

// Each thread: one image n, one output row r, one group of 4 output cols.
// Loads 2 float4 from input row 2r and 2 float4 from row 2r+1 (8 input cols),
// produces one float4 per band. Warp covers a full 256-col input row pair.
__global__ void __launch_bounds__(512) dwt2d_haar_kernel(
    const float* __restrict__ x, float* __restrict__ out)
{
    int t = blockIdx.x * blockDim.x + threadIdx.x;
    // t layout: [n:10][r:7][v:5]  (1024 * 128 * 32 = 4,194,304 threads)
    int v = t & 31;          // 0..31  -> out cols 4v..4v+3, in cols 8v..8v+7
    int r = (t >> 5) & 127;  // output row
    int n = t >> 12;         // image index

    const float* base = x + (long long)n * (H * W) + (long long)(2 * r) * W + 8 * v;
    const float4* row0 = reinterpret_cast<const float4*>(base);
    const float4* row1 = reinterpret_cast<const float4*>(base + W);

    // Front-batch 4 independent 16B streaming loads (MLP=4, occupancy-carried)
    float4 a0 = __ldcs(&row0[0]);
    float4 a1 = __ldcs(&row0[1]);
    float4 b0 = __ldcs(&row1[0]);
    float4 b1 = __ldcs(&row1[1]);

    float4 ll, lh, hl, hh;

    {   // pair 0: a0.xy / b0.xy
        float st = a0.x + a0.y, dt = a0.x - a0.y;
        float sb = b0.x + b0.y, db = b0.x - b0.y;
        ll.x = 0.5f * (st + sb); lh.x = 0.5f * (dt + db);
        hl.x = 0.5f * (st - sb); hh.x = 0.5f * (dt - db);
    }
    {   // pair 1: a0.zw / b0.zw
        float st = a0.z + a0.w, dt = a0.z - a0.w;
        float sb = b0.z + b0.w, db = b0.z - b0.w;
        ll.y = 0.5f * (st + sb); lh.y = 0.5f * (dt + db);
        hl.y = 0.5f * (st - sb); hh.y = 0.5f * (dt - db);
    }
    {   // pair 2: a1.xy / b1.xy
        float st = a1.x + a1.y, dt = a1.x - a1.y;
        float sb = b1.x + b1.y, db = b1.x - b1.y;
        ll.z = 0.5f * (st + sb); lh.z = 0.5f * (dt + db);
        hl.z = 0.5f * (st - sb); hh.z = 0.5f * (dt - db);
    }
    {   // pair 3: a1.zw / b1.zw
        float st = a1.z + a1.w, dt = a1.z - a1.w;
        float sb = b1.z + b1.w, db = b1.z - b1.w;
        ll.w = 0.5f * (st + sb); lh.w = 0.5f * (dt + db);
        hl.w = 0.5f * (st - sb); hh.w = 0.5f * (dt - db);
    }

    long long o = (long long)n * (LH_ * LW_) + (long long)r * LW_ + 4 * v;
    // bands concatenated: LL, LH, HL, HH — default-policy stores (L2 buffers
    // dirty lines; write-back batching reduces DRAM bus turnaround)
    *reinterpret_cast<float4*>(out + o)            = ll;
    *reinterpret_cast<float4*>(out + o + BAND)     = lh;
    *reinterpret_cast<float4*>(out + o + 2 * BAND) = hl;
    *reinterpret_cast<float4*>(out + o + 3 * BAND) = hh;
}

extern "C" void kernel_launch(void* const* d_in, const int* in_sizes, int n_in,
                              void* d_out, int out_size)
{
    const float* x = (const float*)d_in[0];   // (16,64,256,256) fp32
    float* out = (float*)d_out;               // 4 bands concatenated

    const int total = NIMG * LH_ * 32;        // 4,194,304 threads
    const int threads = 512;
    const int blocks = total / threads;       // 8192
    dwt2d_haar_kernel<<<blocks, threads>>>(x, out);
}